// round 9
// baseline (speedup 1.0000x reference)
#include <cuda_runtime.h>
#include <cuda_fp16.h>
#include <cstdint>

#define IN_F 4096
#define OUT_F 4096
#define MAX_T 8192

#define BM 128
#define BN 128
#define BK 64
#define KSTRIDE (BK + 16)     // 80-byte smem row stride: conflict-free lane map
#define KT (IN_F / BK)        // 64 k-tiles per tile
#define NTB (OUT_F / BN)      // 32 n-blocks
#define A_STAGE (BM * KSTRIDE)                 // 10240 B
#define B_STAGE (BN * KSTRIDE)                 // 10240 B
#define GEMM_SMEM (3 * (A_STAGE + B_STAGE))    // 61440 B dynamic

#define REPACK_BLOCKS ((OUT_F * IN_F / 4) / 256)   // 16384

// Scratch (device globals: allocations are banned in kernel_launch)
__device__ __align__(16) int8_t g_qx[(size_t)MAX_T * IN_F];
__device__ __align__(16) int8_t g_qw[(size_t)OUT_F * IN_F];
__device__ float g_xs[MAX_T];
__device__ int g_x_is_f32;
__device__ int g_w_is_i32;

__device__ __forceinline__ void cp16(uint32_t dst, const void* src) {
    asm volatile("cp.async.cg.shared.global [%0], [%1], 16;\n" ::"r"(dst), "l"(src));
}
#define CP_COMMIT() asm volatile("cp.async.commit_group;\n")
#define CP_WAIT(n)  asm volatile("cp.async.wait_group %0;\n" ::"n"(n))

// ---------------------------------------------------------------------------
// Kernel 0: dtype detection, parallel (harness may promote fp16->fp32,
// int8->int32). Deterministic pure function of the inputs.
// ---------------------------------------------------------------------------
__global__ void detect_kernel(const void* xv, const void* wv) {
    __shared__ float sm[8];
    __shared__ int bad;
    int tid = threadIdx.x;
    if (tid == 0) bad = 0;
    __syncthreads();

    const float* xf = (const float*)xv;
    float m = 0.f;
#pragma unroll
    for (int i = 0; i < 16; i++) m = fmaxf(m, fabsf(xf[tid + 256 * i]));
#pragma unroll
    for (int o = 16; o > 0; o >>= 1) m = fmaxf(m, __shfl_xor_sync(~0u, m, o));
    int lane = tid & 31, wid = tid >> 5;
    if (lane == 0) sm[wid] = m;

    const int* wi = (const int*)wv;
    int v = wi[tid];
    if (v < -128 || v > 127) bad = 1;
    __syncthreads();

    if (tid == 0) {
        float mx = sm[0];
#pragma unroll
        for (int i = 1; i < 8; i++) mx = fmaxf(mx, sm[i]);
        g_x_is_f32 = (mx < 8.0f) ? 1 : 0;
        g_w_is_i32 = bad ? 0 : 1;
    }
}

// ---------------------------------------------------------------------------
// Kernel 1: FUSED weight repack (int32->int8) + per-token quantization.
// ---------------------------------------------------------------------------
__global__ void prep_kernel(const void* xv, const void* wv, int T) {
    if (blockIdx.x < REPACK_BLOCKS) {
        if (!g_w_is_i32) return;
        size_t idx = (size_t)blockIdx.x * blockDim.x + threadIdx.x;
        int4 v = ((const int4*)wv)[idx];
        char4 c;
        c.x = (char)v.x; c.y = (char)v.y; c.z = (char)v.z; c.w = (char)v.w;
        reinterpret_cast<char4*>(g_qw)[idx] = c;
        return;
    }
    int t = blockIdx.x - REPACK_BLOCKS;
    if (t >= T) return;
    int tid = threadIdx.x;
    float vals[16];
    if (g_x_is_f32) {
        const float4* row = reinterpret_cast<const float4*>((const float*)xv + (size_t)t * IN_F);
#pragma unroll
        for (int i = 0; i < 4; i++) {
            float4 v = row[tid * 4 + i];
            vals[4 * i] = v.x; vals[4 * i + 1] = v.y;
            vals[4 * i + 2] = v.z; vals[4 * i + 3] = v.w;
        }
    } else {
        const float4* row = reinterpret_cast<const float4*>((const __half*)xv + (size_t)t * IN_F);
        float4 v0 = row[tid * 2], v1 = row[tid * 2 + 1];
        const __half2* h0 = (const __half2*)&v0;
        const __half2* h1 = (const __half2*)&v1;
#pragma unroll
        for (int i = 0; i < 4; i++) {
            float2 f = __half22float2(h0[i]);
            vals[2 * i] = f.x; vals[2 * i + 1] = f.y;
        }
#pragma unroll
        for (int i = 0; i < 4; i++) {
            float2 f = __half22float2(h1[i]);
            vals[8 + 2 * i] = f.x; vals[8 + 2 * i + 1] = f.y;
        }
    }
    float m = 0.f;
#pragma unroll
    for (int i = 0; i < 16; i++) m = fmaxf(m, fabsf(vals[i]));
#pragma unroll
    for (int o = 16; o > 0; o >>= 1) m = fmaxf(m, __shfl_xor_sync(~0u, m, o));
    __shared__ float sm[8];
    int lane = tid & 31, wid = tid >> 5;
    if (lane == 0) sm[wid] = m;
    __syncthreads();
    if (tid < 8) {
        float v = sm[tid];
#pragma unroll
        for (int o = 4; o > 0; o >>= 1) v = fmaxf(v, __shfl_xor_sync(0xffu, v, o));
        if (tid == 0) sm[0] = v;
    }
    __syncthreads();
    float scale = sm[0] / 127.0f;
    if (tid == 0) g_xs[t] = scale;
    int8_t q[16];
#pragma unroll
    for (int i = 0; i < 16; i++) {
        float r = rintf(__fdiv_rn(vals[i], scale));
        r = fminf(fmaxf(r, -128.f), 127.f);
        q[i] = (int8_t)(int)r;
    }
    *reinterpret_cast<int4*>(g_qx + (size_t)t * IN_F + tid * 16) =
        *reinterpret_cast<const int4*>(q);
}

// ---------------------------------------------------------------------------
// Kernel 2: PERSISTENT int8 GEMM. grid = 2*SMs, each CTA loops tiles
// cta, cta+G, ... The 3-stage/1-sync cp.async pipeline (validated in R8)
// runs continuously ACROSS tile boundaries: during the last two k-iters of
// tile t the cursor prefetches tile t+G's stages, hiding epilogue + switch.
// Inner compute body is byte-identical to the 91.5%-tensor R7/R8 body.
// ---------------------------------------------------------------------------
__global__ void __launch_bounds__(256, 2)
gemm_kernel(const void* Worig, const void* wscv, const void* biasv,
            void* Yv, int T) {
    extern __shared__ __align__(128) int8_t dsm[];

    int tid = threadIdx.x;
    const int8_t* W = g_w_is_i32 ? g_qw : (const int8_t*)Worig;
    int G = gridDim.x;
    int ntiles = NTB * ((T + BM - 1) / BM);

    // rotating stage pointers
    int8_t* aCur = dsm;
    int8_t* aNxt = dsm + (A_STAGE + B_STAGE);
    int8_t* aFut = dsm + 2 * (A_STAGE + B_STAGE);

    // per-thread loader coords
    int lr0 = tid >> 2, lp0 = (tid & 3) * 16;
    int lr1 = (tid + 256) >> 2;
    uint32_t so0 = lr0 * KSTRIDE + lp0;
    uint32_t so1 = lr1 * KSTRIDE + lp0;

    auto load_tile = [&](int8_t* stage, int lt, int lk) {
        int m0 = (lt / NTB) * BM;
        int n0 = (lt % NTB) * BN;
        int k0 = lk * BK;
        uint32_t ab = (uint32_t)__cvta_generic_to_shared(stage);
        uint32_t bb = ab + A_STAGE;
        cp16(ab + so0, g_qx + (size_t)(m0 + lr0) * IN_F + k0 + lp0);
        cp16(ab + so1, g_qx + (size_t)(m0 + lr1) * IN_F + k0 + lp0);
        cp16(bb + so0, W + (size_t)(n0 + lr0) * IN_F + k0 + lp0);
        cp16(bb + so1, W + (size_t)(n0 + lr1) * IN_F + k0 + lp0);
    };

    int lane = tid & 31;
    int warp = tid >> 5;
    int wm = (warp & 3) * 32;
    int wn = (warp >> 2) * 64;
    int quad = lane >> 2;
    int four = (lane & 3) * 4;
    bool f32io = (g_x_is_f32 != 0);

    int myFirst = blockIdx.x;
    if (myFirst >= ntiles) return;

    // load cursor (tile, k) — runs 2 iterations ahead of compute
    int lt = myFirst, lk = 0;
    auto advance = [&]() {
        if (++lk == KT) { lk = 0; lt += G; }
    };

    // prologue: fill 2 stages
    load_tile(aCur, lt, lk); CP_COMMIT(); advance();
    load_tile(aNxt, lt, lk); CP_COMMIT(); advance();
    CP_WAIT(1);

    for (int t = myFirst; t < ntiles; t += G) {
        int c[2][8][4];
#pragma unroll
        for (int mt = 0; mt < 2; mt++)
#pragma unroll
            for (int nt = 0; nt < 8; nt++)
#pragma unroll
                for (int i = 0; i < 4; i++) c[mt][nt][i] = 0;

        for (int kt = 0; kt < KT; ++kt) {
            __syncthreads();   // RAW publish current stage; WAR fence aFut

            bool issued = (lt < ntiles);
            if (issued) { load_tile(aFut, lt, lk); CP_COMMIT(); advance(); }

            const int8_t* pA = aCur;
            const int8_t* pB = aCur + A_STAGE;

#pragma unroll
            for (int kk = 0; kk < BK; kk += 32) {
                int a[2][4];
#pragma unroll
                for (int mt = 0; mt < 2; ++mt) {
                    const int8_t* base = pA + (wm + mt * 16 + quad) * KSTRIDE + kk + four;
                    a[mt][0] = *reinterpret_cast<const int*>(base);
                    a[mt][1] = *reinterpret_cast<const int*>(base + 8 * KSTRIDE);
                    a[mt][2] = *reinterpret_cast<const int*>(base + 16);
                    a[mt][3] = *reinterpret_cast<const int*>(base + 8 * KSTRIDE + 16);
                }
                int b[8][2];
#pragma unroll
                for (int nt = 0; nt < 8; ++nt) {
                    const int8_t* base = pB + (wn + nt * 8 + quad) * KSTRIDE + kk + four;
                    b[nt][0] = *reinterpret_cast<const int*>(base);
                    b[nt][1] = *reinterpret_cast<const int*>(base + 16);
                }
#pragma unroll
                for (int mt = 0; mt < 2; ++mt)
#pragma unroll
                    for (int nt = 0; nt < 8; ++nt)
                        asm volatile(
                            "mma.sync.aligned.m16n8k32.row.col.s32.s8.s8.s32 "
                            "{%0,%1,%2,%3},{%4,%5,%6,%7},{%8,%9},{%0,%1,%2,%3};\n"
                            : "+r"(c[mt][nt][0]), "+r"(c[mt][nt][1]),
                              "+r"(c[mt][nt][2]), "+r"(c[mt][nt][3])
                            : "r"(a[mt][0]), "r"(a[mt][1]), "r"(a[mt][2]), "r"(a[mt][3]),
                              "r"(b[nt][0]), "r"(b[nt][1]));
            }

            if (issued) CP_WAIT(1);   // next stage (this thread) complete
            else        CP_WAIT(0);   // drain remaining tail groups

            int8_t* t0 = aCur; aCur = aNxt; aNxt = aFut; aFut = t0;
        }

        // Epilogue for tile t (registers + global only; smem pipeline live)
        int m0 = (t / NTB) * BM;
        int n0 = (t % NTB) * BN;
#pragma unroll
        for (int mt = 0; mt < 2; ++mt) {
            int r0 = m0 + wm + mt * 16 + quad;
            float xs0 = g_xs[r0], xs1 = g_xs[r0 + 8];
#pragma unroll
            for (int nt = 0; nt < 8; ++nt) {
                int cg = n0 + wn + nt * 8 + (lane & 3) * 2;
                float w0, w1;
                __half b0, b1;
                if (f32io) {
                    w0 = ((const float*)wscv)[cg]; w1 = ((const float*)wscv)[cg + 1];
                    b0 = __float2half(((const float*)biasv)[cg]);
                    b1 = __float2half(((const float*)biasv)[cg + 1]);
                } else {
                    w0 = __half2float(((const __half*)wscv)[cg]);
                    w1 = __half2float(((const __half*)wscv)[cg + 1]);
                    b0 = ((const __half*)biasv)[cg];
                    b1 = ((const __half*)biasv)[cg + 1];
                }
                __half y00 = __hadd(__float2half((float)c[mt][nt][0] * w0 * xs0), b0);
                __half y01 = __hadd(__float2half((float)c[mt][nt][1] * w1 * xs0), b1);
                __half y10 = __hadd(__float2half((float)c[mt][nt][2] * w0 * xs1), b0);
                __half y11 = __hadd(__float2half((float)c[mt][nt][3] * w1 * xs1), b1);
                if (f32io) {
                    float* Y = (float*)Yv;
                    if (r0 < T) *reinterpret_cast<float2*>(Y + (size_t)r0 * OUT_F + cg) =
                        make_float2(__half2float(y00), __half2float(y01));
                    if (r0 + 8 < T) *reinterpret_cast<float2*>(Y + (size_t)(r0 + 8) * OUT_F + cg) =
                        make_float2(__half2float(y10), __half2float(y11));
                } else {
                    __half* Y = (__half*)Yv;
                    if (r0 < T) { __half2 o; o.x = y00; o.y = y01;
                        *reinterpret_cast<__half2*>(Y + (size_t)r0 * OUT_F + cg) = o; }
                    if (r0 + 8 < T) { __half2 o; o.x = y10; o.y = y11;
                        *reinterpret_cast<__half2*>(Y + (size_t)(r0 + 8) * OUT_F + cg) = o; }
                }
            }
        }
    }
}

// ---------------------------------------------------------------------------
extern "C" void kernel_launch(void* const* d_in, const int* in_sizes, int n_in,
                              void* d_out, int out_size) {
    const void* x    = d_in[0];
    const void* w    = d_in[1];
    const void* wsc  = d_in[2];
    const void* bias = d_in[3];
    int T = in_sizes[0] / IN_F;

    cudaFuncSetAttribute(gemm_kernel,
        cudaFuncAttributeMaxDynamicSharedMemorySize, GEMM_SMEM);

    int smCount = 148;
    cudaDeviceGetAttribute(&smCount, cudaDevAttrMultiProcessorCount, 0);

    detect_kernel<<<1, 256>>>(x, w);
    prep_kernel<<<REPACK_BLOCKS + T, 256>>>(x, w, T);

    int ntiles = NTB * ((T + BM - 1) / BM);
    int G = 2 * smCount;
    if (G > ntiles) G = ntiles;
    gemm_kernel<<<G, 256, GEMM_SMEM>>>(w, wsc, bias, d_out, T);
}

// round 10
// speedup vs baseline: 1.0691x; 1.0691x over previous
#include <cuda_runtime.h>
#include <cuda_fp16.h>
#include <cstdint>

#define IN_F 4096
#define OUT_F 4096
#define MAX_T 8192

#define BM 128
#define BN 128
#define BK 64
#define KSTRIDE (BK + 16)     // 80-byte smem row stride: conflict-free ldmatrix
#define KT (IN_F / BK)        // 64 k-tiles
#define A_STAGE (BM * KSTRIDE)                 // 10240 B
#define B_STAGE (BN * KSTRIDE)                 // 10240 B
#define GEMM_SMEM (3 * (A_STAGE + B_STAGE))    // 61440 B dynamic

#define REPACK_BLOCKS ((OUT_F * IN_F / 4) / 256)   // 16384

// Scratch (device globals: allocations are banned in kernel_launch)
__device__ __align__(16) int8_t g_qx[(size_t)MAX_T * IN_F];
__device__ __align__(16) int8_t g_qw[(size_t)OUT_F * IN_F];
__device__ float g_xs[MAX_T];
__device__ int g_x_is_f32;
__device__ int g_w_is_i32;

__device__ __forceinline__ void cp16(uint32_t dst, const void* src) {
    asm volatile("cp.async.cg.shared.global [%0], [%1], 16;\n" ::"r"(dst), "l"(src));
}
#define CP_COMMIT() asm volatile("cp.async.commit_group;\n")
#define CP_WAIT(n)  asm volatile("cp.async.wait_group %0;\n" ::"n"(n))

// ---------------------------------------------------------------------------
// Kernel 0: dtype detection, parallel (harness may promote fp16->fp32,
// int8->int32). Deterministic pure function of the inputs.
// ---------------------------------------------------------------------------
__global__ void detect_kernel(const void* xv, const void* wv) {
    __shared__ float sm[8];
    __shared__ int bad;
    int tid = threadIdx.x;
    if (tid == 0) bad = 0;
    __syncthreads();

    const float* xf = (const float*)xv;
    float m = 0.f;
#pragma unroll
    for (int i = 0; i < 16; i++) m = fmaxf(m, fabsf(xf[tid + 256 * i]));
#pragma unroll
    for (int o = 16; o > 0; o >>= 1) m = fmaxf(m, __shfl_xor_sync(~0u, m, o));
    int lane = tid & 31, wid = tid >> 5;
    if (lane == 0) sm[wid] = m;

    const int* wi = (const int*)wv;
    int v = wi[tid];
    if (v < -128 || v > 127) bad = 1;
    __syncthreads();

    if (tid == 0) {
        float mx = sm[0];
#pragma unroll
        for (int i = 1; i < 8; i++) mx = fmaxf(mx, sm[i]);
        g_x_is_f32 = (mx < 8.0f) ? 1 : 0;
        g_w_is_i32 = bad ? 0 : 1;
    }
}

// ---------------------------------------------------------------------------
// Kernel 1: FUSED weight repack (int32->int8) + per-token quantization.
// ---------------------------------------------------------------------------
__global__ void prep_kernel(const void* xv, const void* wv, int T) {
    if (blockIdx.x < REPACK_BLOCKS) {
        if (!g_w_is_i32) return;
        size_t idx = (size_t)blockIdx.x * blockDim.x + threadIdx.x;
        int4 v = ((const int4*)wv)[idx];
        char4 c;
        c.x = (char)v.x; c.y = (char)v.y; c.z = (char)v.z; c.w = (char)v.w;
        reinterpret_cast<char4*>(g_qw)[idx] = c;
        return;
    }
    int t = blockIdx.x - REPACK_BLOCKS;
    if (t >= T) return;
    int tid = threadIdx.x;
    float vals[16];
    if (g_x_is_f32) {
        const float4* row = reinterpret_cast<const float4*>((const float*)xv + (size_t)t * IN_F);
#pragma unroll
        for (int i = 0; i < 4; i++) {
            float4 v = row[tid * 4 + i];
            vals[4 * i] = v.x; vals[4 * i + 1] = v.y;
            vals[4 * i + 2] = v.z; vals[4 * i + 3] = v.w;
        }
    } else {
        const float4* row = reinterpret_cast<const float4*>((const __half*)xv + (size_t)t * IN_F);
        float4 v0 = row[tid * 2], v1 = row[tid * 2 + 1];
        const __half2* h0 = (const __half2*)&v0;
        const __half2* h1 = (const __half2*)&v1;
#pragma unroll
        for (int i = 0; i < 4; i++) {
            float2 f = __half22float2(h0[i]);
            vals[2 * i] = f.x; vals[2 * i + 1] = f.y;
        }
#pragma unroll
        for (int i = 0; i < 4; i++) {
            float2 f = __half22float2(h1[i]);
            vals[8 + 2 * i] = f.x; vals[8 + 2 * i + 1] = f.y;
        }
    }
    float m = 0.f;
#pragma unroll
    for (int i = 0; i < 16; i++) m = fmaxf(m, fabsf(vals[i]));
#pragma unroll
    for (int o = 16; o > 0; o >>= 1) m = fmaxf(m, __shfl_xor_sync(~0u, m, o));
    __shared__ float sm[8];
    int lane = tid & 31, wid = tid >> 5;
    if (lane == 0) sm[wid] = m;
    __syncthreads();
    if (tid < 8) {
        float v = sm[tid];
#pragma unroll
        for (int o = 4; o > 0; o >>= 1) v = fmaxf(v, __shfl_xor_sync(0xffu, v, o));
        if (tid == 0) sm[0] = v;
    }
    __syncthreads();
    float scale = sm[0] / 127.0f;
    if (tid == 0) g_xs[t] = scale;
    int8_t q[16];
#pragma unroll
    for (int i = 0; i < 16; i++) {
        float r = rintf(__fdiv_rn(vals[i], scale));
        r = fminf(fmaxf(r, -128.f), 127.f);
        q[i] = (int8_t)(int)r;
    }
    *reinterpret_cast<int4*>(g_qx + (size_t)t * IN_F + tid * 16) =
        *reinterpret_cast<const int4*>(q);
}

// ---------------------------------------------------------------------------
// Kernel 2: int8 GEMM — R8 3-stage/1-sync pipeline, fragments via
// ldmatrix.x4 (mapping empirically equivalent to the verified direct-LDS
// layout: R1 vs R2 produced bit-identical output). 4x fewer smem-load
// instructions per k-tile (48 LDS -> 12 ldmatrix per warp).
// Bank analysis: rows at stride 80B -> row i starts at bank 20i mod 32;
// the 8 rows of one m8n8 matrix occupy disjoint 4-bank groups.
// 8 warps: 4(M) x 2(N); warp tile 32x64; per-warp mma grid 2x8.
// ---------------------------------------------------------------------------
__global__ void __launch_bounds__(256, 2)
gemm_kernel(const void* Worig, const void* wscv, const void* biasv,
            void* Yv, int T) {
    extern __shared__ __align__(128) int8_t dsm[];

    int tid = threadIdx.x;
    int m0 = blockIdx.y * BM;
    int n0 = blockIdx.x * BN;
    const int8_t* W = g_w_is_i32 ? g_qw : (const int8_t*)Worig;

    // rotating stage pointers
    int8_t* aCur = dsm;
    int8_t* aNxt = dsm + (A_STAGE + B_STAGE);
    int8_t* aFut = dsm + 2 * (A_STAGE + B_STAGE);

    // per-thread loader coords (512 16B chunks per operand; 2 per thread)
    int lr0 = tid >> 2, lp0 = (tid & 3) * 16;
    int lr1 = (tid + 256) >> 2;
    uint32_t so0 = lr0 * KSTRIDE + lp0;
    uint32_t so1 = lr1 * KSTRIDE + lp0;

    auto load_tile = [&](int8_t* stage, int k0) {
        uint32_t ab = (uint32_t)__cvta_generic_to_shared(stage);
        uint32_t bb = ab + A_STAGE;
        cp16(ab + so0, g_qx + (size_t)(m0 + lr0) * IN_F + k0 + lp0);
        cp16(ab + so1, g_qx + (size_t)(m0 + lr1) * IN_F + k0 + lp0);
        cp16(bb + so0, W + (size_t)(n0 + lr0) * IN_F + k0 + lp0);
        cp16(bb + so1, W + (size_t)(n0 + lr1) * IN_F + k0 + lp0);
    };

    int lane = tid & 31;
    int warp = tid >> 5;
    int wm = (warp & 3) * 32;
    int wn = (warp >> 2) * 64;
    int quad = lane >> 2;

    // ldmatrix lane addressing (validated R1 mapping)
    int a_row  = wm + (lane & 7) + ((lane >> 3) & 1) * 8;
    int a_koff = ((lane >> 4) & 1) * 16;
    int b_row  = wn + (lane & 7) + ((lane >> 4) & 1) * 8;
    int b_koff = ((lane >> 3) & 1) * 16;

    int c[2][8][4];
#pragma unroll
    for (int mt = 0; mt < 2; mt++)
#pragma unroll
        for (int nt = 0; nt < 8; nt++)
#pragma unroll
            for (int i = 0; i < 4; i++) c[mt][nt][i] = 0;

    load_tile(aCur, 0);
    CP_COMMIT();
    load_tile(aNxt, BK);
    CP_COMMIT();
    CP_WAIT(1);

    for (int kt = 0; kt < KT; ++kt) {
        __syncthreads();        // RAW publish stage kt; WAR fence aFut

        if (kt + 2 < KT) {
            load_tile(aFut, (kt + 2) * BK);
            CP_COMMIT();
        }

        uint32_t aS = (uint32_t)__cvta_generic_to_shared(aCur);
        uint32_t bS = aS + A_STAGE;

#pragma unroll
        for (int kk = 0; kk < BK; kk += 32) {
            uint32_t a[2][4];
#pragma unroll
            for (int mt = 0; mt < 2; ++mt) {
                uint32_t addr = aS + (a_row + mt * 16) * KSTRIDE + kk + a_koff;
                asm volatile(
                    "ldmatrix.sync.aligned.m8n8.x4.shared.b16 {%0,%1,%2,%3}, [%4];\n"
                    : "=r"(a[mt][0]), "=r"(a[mt][1]), "=r"(a[mt][2]), "=r"(a[mt][3])
                    : "r"(addr));
            }
            uint32_t b[8][2];
#pragma unroll
            for (int np = 0; np < 4; ++np) {
                uint32_t addr = bS + (b_row + np * 16) * KSTRIDE + kk + b_koff;
                uint32_t r0, r1, r2, r3;
                asm volatile(
                    "ldmatrix.sync.aligned.m8n8.x4.shared.b16 {%0,%1,%2,%3}, [%4];\n"
                    : "=r"(r0), "=r"(r1), "=r"(r2), "=r"(r3)
                    : "r"(addr));
                b[2 * np][0] = r0; b[2 * np][1] = r1;
                b[2 * np + 1][0] = r2; b[2 * np + 1][1] = r3;
            }
#pragma unroll
            for (int mt = 0; mt < 2; ++mt)
#pragma unroll
                for (int nt = 0; nt < 8; ++nt)
                    asm volatile(
                        "mma.sync.aligned.m16n8k32.row.col.s32.s8.s8.s32 "
                        "{%0,%1,%2,%3},{%4,%5,%6,%7},{%8,%9},{%0,%1,%2,%3};\n"
                        : "+r"(c[mt][nt][0]), "+r"(c[mt][nt][1]),
                          "+r"(c[mt][nt][2]), "+r"(c[mt][nt][3])
                        : "r"(a[mt][0]), "r"(a[mt][1]), "r"(a[mt][2]), "r"(a[mt][3]),
                          "r"(b[nt][0]), "r"(b[nt][1]));
        }

        if (kt + 2 < KT)      CP_WAIT(1);
        else if (kt + 1 < KT) CP_WAIT(0);

        int8_t* t0 = aCur; aCur = aNxt; aNxt = aFut; aFut = t0;
    }

    // Epilogue: y = fp16(q * ws[n] * xs[m]); y += bias[n] in fp16 (as reference)
    bool f32io = (g_x_is_f32 != 0);
#pragma unroll
    for (int mt = 0; mt < 2; ++mt) {
        int r0 = m0 + wm + mt * 16 + quad;
        float xs0 = g_xs[r0], xs1 = g_xs[r0 + 8];
#pragma unroll
        for (int nt = 0; nt < 8; ++nt) {
            int cg = n0 + wn + nt * 8 + (lane & 3) * 2;
            float w0, w1;
            __half b0, b1;
            if (f32io) {
                w0 = ((const float*)wscv)[cg]; w1 = ((const float*)wscv)[cg + 1];
                b0 = __float2half(((const float*)biasv)[cg]);
                b1 = __float2half(((const float*)biasv)[cg + 1]);
            } else {
                w0 = __half2float(((const __half*)wscv)[cg]);
                w1 = __half2float(((const __half*)wscv)[cg + 1]);
                b0 = ((const __half*)biasv)[cg];
                b1 = ((const __half*)biasv)[cg + 1];
            }
            __half y00 = __hadd(__float2half((float)c[mt][nt][0] * w0 * xs0), b0);
            __half y01 = __hadd(__float2half((float)c[mt][nt][1] * w1 * xs0), b1);
            __half y10 = __hadd(__float2half((float)c[mt][nt][2] * w0 * xs1), b0);
            __half y11 = __hadd(__float2half((float)c[mt][nt][3] * w1 * xs1), b1);
            if (f32io) {
                float* Y = (float*)Yv;
                if (r0 < T) *reinterpret_cast<float2*>(Y + (size_t)r0 * OUT_F + cg) =
                    make_float2(__half2float(y00), __half2float(y01));
                if (r0 + 8 < T) *reinterpret_cast<float2*>(Y + (size_t)(r0 + 8) * OUT_F + cg) =
                    make_float2(__half2float(y10), __half2float(y11));
            } else {
                __half* Y = (__half*)Yv;
                if (r0 < T) { __half2 o; o.x = y00; o.y = y01;
                    *reinterpret_cast<__half2*>(Y + (size_t)r0 * OUT_F + cg) = o; }
                if (r0 + 8 < T) { __half2 o; o.x = y10; o.y = y11;
                    *reinterpret_cast<__half2*>(Y + (size_t)(r0 + 8) * OUT_F + cg) = o; }
            }
        }
    }
}

// ---------------------------------------------------------------------------
extern "C" void kernel_launch(void* const* d_in, const int* in_sizes, int n_in,
                              void* d_out, int out_size) {
    const void* x    = d_in[0];
    const void* w    = d_in[1];
    const void* wsc  = d_in[2];
    const void* bias = d_in[3];
    int T = in_sizes[0] / IN_F;

    cudaFuncSetAttribute(gemm_kernel,
        cudaFuncAttributeMaxDynamicSharedMemorySize, GEMM_SMEM);

    detect_kernel<<<1, 256>>>(x, w);
    prep_kernel<<<REPACK_BLOCKS + T, 256>>>(x, w, T);

    dim3 grid(OUT_F / BN, (T + BM - 1) / BM);
    gemm_kernel<<<grid, 256, GEMM_SMEM>>>(w, wsc, bias, d_out, T);
}